// round 10
// baseline (speedup 1.0000x reference)
#include <cuda_runtime.h>
#include <cuda_bf16.h>
#include <cstdint>
#include <math.h>

// ---------------------------------------------------------------------------
// Problem constants
// ---------------------------------------------------------------------------
#define S_LEN   2048
#define D_MODEL 2048
#define L_LAT   512
#define BATCH   2
#define NHEADS  16
#define HDIM    128
#define M_ROWS  (BATCH * S_LEN)   // 4096
#define WINDOW  128
#define PERSIST 16

// ---------------------------------------------------------------------------
// PTX helpers
// ---------------------------------------------------------------------------
__device__ __forceinline__ uint32_t smem_u32(const void* p) {
    uint32_t a;
    asm("{ .reg .u64 t; cvta.to.shared.u64 t, %1; cvt.u32.u64 %0, t; }"
        : "=r"(a) : "l"(p));
    return a;
}

__device__ __forceinline__ void ldsm4(uint32_t* r, uint32_t addr) {
    asm volatile("ldmatrix.sync.aligned.m8n8.x4.shared.b16 {%0,%1,%2,%3}, [%4];"
                 : "=r"(r[0]), "=r"(r[1]), "=r"(r[2]), "=r"(r[3]) : "r"(addr));
}
__device__ __forceinline__ void ldsm4t(uint32_t* r, uint32_t addr) {
    asm volatile("ldmatrix.sync.aligned.m8n8.x4.trans.shared.b16 {%0,%1,%2,%3}, [%4];"
                 : "=r"(r[0]), "=r"(r[1]), "=r"(r[2]), "=r"(r[3]) : "r"(addr));
}

__device__ __forceinline__ void mma16816(float* c, const uint32_t* a, const uint32_t* b) {
    asm volatile("mma.sync.aligned.m16n8k16.row.col.f32.bf16.bf16.f32 "
                 "{%0,%1,%2,%3}, {%4,%5,%6,%7}, {%8,%9}, {%0,%1,%2,%3};"
                 : "+f"(c[0]), "+f"(c[1]), "+f"(c[2]), "+f"(c[3])
                 : "r"(a[0]), "r"(a[1]), "r"(a[2]), "r"(a[3]),
                   "r"(b[0]), "r"(b[1]));
}

// int8 MMA, k=32, s32 accumulate
__device__ __forceinline__ void imma16832(int* c, const uint32_t* a, const uint32_t* b) {
    asm volatile("mma.sync.aligned.m16n8k32.row.col.s32.s8.s8.s32 "
                 "{%0,%1,%2,%3}, {%4,%5,%6,%7}, {%8,%9}, {%0,%1,%2,%3};"
                 : "+r"(c[0]), "+r"(c[1]), "+r"(c[2]), "+r"(c[3])
                 : "r"(a[0]), "r"(a[1]), "r"(a[2]), "r"(a[3]),
                   "r"(b[0]), "r"(b[1]));
}

#define CP_ASYNC16(s, g) \
    asm volatile("cp.async.cg.shared.global [%0], [%1], 16;" :: "r"(s), "l"(g))
#define CP_COMMIT() asm volatile("cp.async.commit_group;" ::: "memory")
#define CP_WAIT0()  asm volatile("cp.async.wait_group 0;" ::: "memory")
#define CP_WAIT1()  asm volatile("cp.async.wait_group 1;" ::: "memory")

__device__ __forceinline__ uint32_t pack_bf2(float a, float b) {
    __nv_bfloat162 v = __halves2bfloat162(__float2bfloat16(a), __float2bfloat16(b));
    return *(uint32_t*)&v;
}
__device__ __forceinline__ void split1(float v, float& hi_f, float& lo_f) {
    __nv_bfloat16 h = __float2bfloat16(v);
    hi_f = __bfloat162float(h);
    lo_f = v - hi_f;
}

// ---------------------------------------------------------------------------
// Scratch buffers
// ---------------------------------------------------------------------------
#define N_XD   ((size_t)M_ROWS * D_MODEL)
#define N_DD   ((size_t)D_MODEL * D_MODEL)
#define N_DL   ((size_t)D_MODEL * L_LAT)
#define N_ML   ((size_t)M_ROWS * L_LAT)

// int8 2-slice operands
__device__ int8_t g_xq1[N_XD],  g_xq2[N_XD];
__device__ int8_t g_kvq1[N_ML], g_kvq2[N_ML];
__device__ int8_t g_aoq1[N_XD], g_aoq2[N_XD];
__device__ int8_t g_Wqt1[N_DD], g_Wqt2[N_DD];     // [N=2048, K=2048]
__device__ int8_t g_Wkvt1[N_DL], g_Wkvt2[N_DL];   // [N=512,  K=2048]
__device__ int8_t g_Wkt1[N_DL], g_Wkt2[N_DL];     // [N=2048, K=512]
__device__ int8_t g_Wvt1[N_DL], g_Wvt2[N_DL];
__device__ int8_t g_Wot1[N_DD], g_Wot2[N_DD];
// scales
__device__ float g_sx[M_ROWS], g_skv[M_ROWS], g_sao[M_ROWS];
__device__ float g_sWq[D_MODEL], g_sWkv[L_LAT], g_sWk[D_MODEL],
                 g_sWv[D_MODEL], g_sWo[D_MODEL];
// fp32 intermediates
__device__ float g_KV[N_ML];
__device__ float g_AO[N_XD];
// bf16 hi/lo for attention
__device__ __nv_bfloat16 g_Qh[N_XD], g_Ql[N_XD];
__device__ __nv_bfloat16 g_Kh[N_XD], g_Kl[N_XD];
__device__ __nv_bfloat16 g_Vh[N_XD], g_Vl[N_XD];

// ---------------------------------------------------------------------------
// Row quantization: X[R,C] fp32 -> q1,q2 int8 (2-slice), sA[R]
// One block per row, 256 threads.
// ---------------------------------------------------------------------------
__global__ __launch_bounds__(256)
void quant_rows(const float* __restrict__ X, int C,
                int8_t* __restrict__ q1, int8_t* __restrict__ q2,
                float* __restrict__ sA)
{
    __shared__ float red[8];
    __shared__ float s_inv, s_val;
    const int row = blockIdx.x;
    const int t = threadIdx.x;
    const float* xr = X + (size_t)row * C;

    float m = 0.0f;
    for (int c = t; c < C; c += 256) m = fmaxf(m, fabsf(xr[c]));
#pragma unroll
    for (int off = 16; off > 0; off >>= 1)
        m = fmaxf(m, __shfl_xor_sync(0xffffffffu, m, off));
    if ((t & 31) == 0) red[t >> 5] = m;
    __syncthreads();
    if (t == 0) {
        float mm = red[0];
#pragma unroll
        for (int i = 1; i < 8; i++) mm = fmaxf(mm, red[i]);
        s_val = (mm > 0.0f) ? mm / 127.0f : 1.0f;
        s_inv = (mm > 0.0f) ? 127.0f / mm : 0.0f;
        sA[row] = s_val;
    }
    __syncthreads();
    const float inv = s_inv;
    for (int c = t; c < C; c += 256) {
        float v = xr[c] * inv;
        int i1 = __float2int_rn(v);
        int i2 = __float2int_rn((v - (float)i1) * 128.0f);
        q1[(size_t)row * C + c] = (int8_t)i1;
        q2[(size_t)row * C + c] = (int8_t)i2;
    }
}

// ---------------------------------------------------------------------------
// Weight quantization: W[K,N] fp32 -> per-column scale sB[N], transposed
// 2-slice int8 outputs Wt1,Wt2 [N,K]. All 5 weights in one launch.
// Block (32,8): 32 columns per block.
// ---------------------------------------------------------------------------
__global__ __launch_bounds__(256)
void quant_weights(const float* __restrict__ Wq,  const float* __restrict__ Wkv,
                   const float* __restrict__ Wk,  const float* __restrict__ Wv,
                   const float* __restrict__ Wo)
{
    __shared__ float red[8][32];
    __shared__ float sinv[32];
    __shared__ int8_t t1[32][33], t2[32][33];

    int b = blockIdx.x;
    const float* W; int K, N; int8_t *o1, *o2; float* sv;
    if (b < 64)       { W = Wq;  K = 2048; N = 2048; o1 = g_Wqt1;  o2 = g_Wqt2;  sv = g_sWq; }
    else if (b < 80)  { b -= 64;  W = Wkv; K = 2048; N = 512;  o1 = g_Wkvt1; o2 = g_Wkvt2; sv = g_sWkv; }
    else if (b < 144) { b -= 80;  W = Wk;  K = 512;  N = 2048; o1 = g_Wkt1;  o2 = g_Wkt2;  sv = g_sWk; }
    else if (b < 208) { b -= 144; W = Wv;  K = 512;  N = 2048; o1 = g_Wvt1;  o2 = g_Wvt2;  sv = g_sWv; }
    else              { b -= 208; W = Wo;  K = 2048; N = 2048; o1 = g_Wot1;  o2 = g_Wot2;  sv = g_sWo; }

    const int tx = threadIdx.x, ty = threadIdx.y;
    const int col = b * 32 + tx;

    // phase 1: column max
    float m = 0.0f;
    for (int k = ty; k < K; k += 8)
        m = fmaxf(m, fabsf(W[(size_t)k * N + col]));
    red[ty][tx] = m;
    __syncthreads();
    if (ty == 0) {
        float mm = red[0][tx];
#pragma unroll
        for (int i = 1; i < 8; i++) mm = fmaxf(mm, red[i][tx]);
        sv[col]  = (mm > 0.0f) ? mm / 127.0f : 1.0f;
        sinv[tx] = (mm > 0.0f) ? 127.0f / mm : 0.0f;
    }
    __syncthreads();
    const float inv = sinv[tx];

    // phase 2: quantize + transpose through smem, coalesced writes
    for (int kt = 0; kt < K; kt += 32) {
#pragma unroll
        for (int j = 0; j < 4; j++) {
            int k = kt + ty + 8 * j;
            float v = W[(size_t)k * N + col] * inv;
            int i1 = __float2int_rn(v);
            int i2 = __float2int_rn((v - (float)i1) * 128.0f);
            t1[ty + 8 * j][tx] = (int8_t)i1;
            t2[ty + 8 * j][tx] = (int8_t)i2;
        }
        __syncthreads();
#pragma unroll
        for (int j = 0; j < 4; j++) {
            int n = ty + 8 * j;
            size_t o = (size_t)(b * 32 + n) * K + kt + tx;
            o1[o] = t1[tx][n];
            o2[o] = t2[tx][n];
        }
        __syncthreads();
    }
}

// ---------------------------------------------------------------------------
// int8 2-slice GEMM: C[M,N] = A[M,K] @ B[K,N]; A as (a1,a2) row-quant int8,
// B as transposed (bt1,bt2)[N,K] col-quant int8.
// Block 128x64, BK=128 bytes, 256 threads = 8 warps (warp 32x32, 4m x 2n),
// 2-stage cp.async, 96 KB smem -> 2 CTAs/SM.
// C = sA[r]*sB[c]*(P + Q/128);  P = sum a1*b1, Q = sum a1*b2 + a2*b1.
// MODE 0: fp32 C out.  MODE 1: split-bf16 (Ch, Cl) out.
// DUAL 1: blocks bx >= nx1 run second GEMM (B2/sB2/C2 outs, N2dim).
// ---------------------------------------------------------------------------
#define GI_A_BYTES (128 * 128)     // 16 KB per A slice tile
#define GI_B_BYTES (64 * 128)      //  8 KB per B slice tile
#define GI_STAGE   (2 * GI_A_BYTES + 2 * GI_B_BYTES)   // 48 KB
#define GI_SMEM    (2 * GI_STAGE)                       // 96 KB

__device__ __forceinline__ void stage_a8(uint32_t sdst, const int8_t* __restrict__ g,
                                         int ldK, int t)
{
#pragma unroll
    for (int j = 0; j < 4; j++) {
        int id = t + 256 * j;          // 0..1023
        int r = id >> 3, u = id & 7;
        uint32_t off = (uint32_t)(r * 128 + u * 16);
        off ^= (off >> 3) & 0x70;
        CP_ASYNC16(sdst + off, g + (size_t)r * ldK + u * 16);
    }
}

__device__ __forceinline__ void stage_b8(uint32_t sdst, const int8_t* __restrict__ g,
                                         int ldK, int t)
{
#pragma unroll
    for (int j = 0; j < 2; j++) {
        int id = t + 256 * j;          // 0..511
        int r = id >> 3, u = id & 7;   // r: 0..63 N-rows
        uint32_t off = (uint32_t)(r * 128 + u * 16);
        off ^= (off >> 3) & 0x70;
        CP_ASYNC16(sdst + off, g + (size_t)r * ldK + u * 16);
    }
}

template <int MODE, int DUAL>
__global__ __launch_bounds__(256, 2)
void gemm_i8(const int8_t* __restrict__ A1, const int8_t* __restrict__ A2,
             const float* __restrict__ sA,
             const int8_t* __restrict__ B1, const int8_t* __restrict__ B2,
             const float* __restrict__ sB,
             float* __restrict__ C, __nv_bfloat16* __restrict__ Ch,
             __nv_bfloat16* __restrict__ Cl,
             const int8_t* __restrict__ B21, const int8_t* __restrict__ B22,
             const float* __restrict__ sB2,
             float* __restrict__ C2, __nv_bfloat16* __restrict__ C2h,
             __nv_bfloat16* __restrict__ C2l,
             int N1dim, int N2dim, int Kdim, int nx1)
{
    extern __shared__ char smc[];
    const uint32_t sb = smem_u32(smc);
    const int t    = threadIdx.x;
    const int lane = t & 31;
    const int w    = t >> 5;

    int bx = blockIdx.x;
    int Ndim = N1dim;
    const int8_t* Bu1 = B1; const int8_t* Bu2 = B2;
    const float* sBu = sB;
    float* Cu = C; __nv_bfloat16* Chu = Ch; __nv_bfloat16* Clu = Cl;
    if (DUAL) {
        if (bx >= nx1) {
            bx -= nx1; Ndim = N2dim;
            Bu1 = B21; Bu2 = B22; sBu = sB2;
            Cu = C2; Chu = C2h; Clu = C2l;
        }
    }

    const int bm = blockIdx.y * 128;
    const int bn = bx * 64;
    const int m0 = (w & 3) * 32;
    const int n0 = (w >> 2) * 32;

    const int8_t* A1p = A1 + (size_t)bm * Kdim;
    const int8_t* A2p = A2 + (size_t)bm * Kdim;
    const int8_t* B1p = Bu1 + (size_t)bn * Kdim;
    const int8_t* B2p = Bu2 + (size_t)bn * Kdim;

    // A ldmatrix geometry (rows of 128 bytes, SW128)
    const uint32_t mask = (uint32_t)((lane & 7) << 4);
    const uint32_t akx  = (uint32_t)(((lane >> 4) & 1) * 16);
    uint32_t arow[2];
#pragma unroll
    for (int mt = 0; mt < 2; mt++)
        arow[mt] = (uint32_t)((m0 + 16 * mt + (lane & 7) + ((lane >> 3) & 1) * 8) * 128);
    // B ldmatrix geometry (Bt rows = N, validated R3 layout)
    const uint32_t bkx = (uint32_t)(((lane >> 3) & 1) * 16);
    uint32_t brow[2];
#pragma unroll
    for (int p = 0; p < 2; p++)
        brow[p] = (uint32_t)((n0 + 16 * p + (lane & 7) + ((lane >> 4) & 1) * 8) * 128);

    int P[2][4][4], Q[2][4][4];
#pragma unroll
    for (int mt = 0; mt < 2; mt++)
#pragma unroll
        for (int nt = 0; nt < 4; nt++)
#pragma unroll
            for (int i = 0; i < 4; i++) { P[mt][nt][i] = 0; Q[mt][nt][i] = 0; }

    const int nch = Kdim >> 7;   // 128-byte K chunks

    // prologue: stage chunk 0
    stage_a8(sb + 0,                           A1p, Kdim, t);
    stage_a8(sb + GI_A_BYTES,                  A2p, Kdim, t);
    stage_b8(sb + 2 * GI_A_BYTES,              B1p, Kdim, t);
    stage_b8(sb + 2 * GI_A_BYTES + GI_B_BYTES, B2p, Kdim, t);
    CP_COMMIT();

    int stg = 0;
    for (int c = 0; c < nch; ++c) {
        if (c + 1 < nch) {
            uint32_t nb = sb + (uint32_t)((stg ^ 1) * GI_STAGE);
            size_t ko = (size_t)(c + 1) * 128;
            stage_a8(nb + 0,                           A1p + ko, Kdim, t);
            stage_a8(nb + GI_A_BYTES,                  A2p + ko, Kdim, t);
            stage_b8(nb + 2 * GI_A_BYTES,              B1p + ko, Kdim, t);
            stage_b8(nb + 2 * GI_A_BYTES + GI_B_BYTES, B2p + ko, Kdim, t);
            CP_COMMIT();
            CP_WAIT1();
        } else {
            CP_WAIT0();
        }
        __syncthreads();

        const uint32_t base = sb + (uint32_t)(stg * GI_STAGE);
        const uint32_t sA1 = base;
        const uint32_t sA2 = base + GI_A_BYTES;
        const uint32_t sB1 = base + 2 * GI_A_BYTES;
        const uint32_t sB2v = base + 2 * GI_A_BYTES + GI_B_BYTES;

#pragma unroll
        for (int s = 0; s < 4; s++) {                 // 4 x k32 per 128B chunk
            const uint32_t ka = ((uint32_t)(32 * s) + akx) ^ mask;
            const uint32_t kB = ((uint32_t)(32 * s) + bkx) ^ mask;

            uint32_t a1[2][4], a2[2][4], b1[4][2], b2[4][2];
#pragma unroll
            for (int mt = 0; mt < 2; mt++) {
                ldsm4(a1[mt], sA1 + arow[mt] + ka);
                ldsm4(a2[mt], sA2 + arow[mt] + ka);
            }
#pragma unroll
            for (int p = 0; p < 2; p++) {
                uint32_t r[4];
                ldsm4(r, sB1 + brow[p] + kB);
                b1[2 * p][0] = r[0]; b1[2 * p][1] = r[1];
                b1[2 * p + 1][0] = r[2]; b1[2 * p + 1][1] = r[3];
                ldsm4(r, sB2v + brow[p] + kB);
                b2[2 * p][0] = r[0]; b2[2 * p][1] = r[1];
                b2[2 * p + 1][0] = r[2]; b2[2 * p + 1][1] = r[3];
            }
#pragma unroll
            for (int mt = 0; mt < 2; mt++)
#pragma unroll
                for (int nt = 0; nt < 4; nt++)
                    imma16832(P[mt][nt], a1[mt], b1[nt]);
#pragma unroll
            for (int mt = 0; mt < 2; mt++)
#pragma unroll
                for (int nt = 0; nt < 4; nt++)
                    imma16832(Q[mt][nt], a1[mt], b2[nt]);
#pragma unroll
            for (int mt = 0; mt < 2; mt++)
#pragma unroll
                for (int nt = 0; nt < 4; nt++)
                    imma16832(Q[mt][nt], a2[mt], b1[nt]);
        }
        __syncthreads();
        stg ^= 1;
    }

    // epilogue: C = sA*sB*(P + Q/128)
    const int rbase = bm + m0 + (lane >> 2);
    const int cbase = bn + n0 + (lane & 3) * 2;
#pragma unroll
    for (int mt = 0; mt < 2; mt++) {
        const int r0 = rbase + 16 * mt;
        const float sa0 = sA[r0], sa1 = sA[r0 + 8];
#pragma unroll
        for (int nt = 0; nt < 4; nt++) {
            const int cc = cbase + 8 * nt;
            const float sb0 = sBu[cc], sb1 = sBu[cc + 1];
            float v0 = sa0 * sb0 * ((float)P[mt][nt][0] + (float)Q[mt][nt][0] * 0.0078125f);
            float v1 = sa0 * sb1 * ((float)P[mt][nt][1] + (float)Q[mt][nt][1] * 0.0078125f);
            float v2 = sa1 * sb0 * ((float)P[mt][nt][2] + (float)Q[mt][nt][2] * 0.0078125f);
            float v3 = sa1 * sb1 * ((float)P[mt][nt][3] + (float)Q[mt][nt][3] * 0.0078125f);
            if (MODE == 0) {
                *(float2*)(Cu + (size_t)r0 * Ndim + cc)       = make_float2(v0, v1);
                *(float2*)(Cu + (size_t)(r0 + 8) * Ndim + cc) = make_float2(v2, v3);
            } else {
                float h0, l0, h1, l1;
                split1(v0, h0, l0); split1(v1, h1, l1);
                *(uint32_t*)(Chu + (size_t)r0 * Ndim + cc) = pack_bf2(h0, h1);
                *(uint32_t*)(Clu + (size_t)r0 * Ndim + cc) = pack_bf2(l0, l1);
                split1(v2, h0, l0); split1(v3, h1, l1);
                *(uint32_t*)(Chu + (size_t)(r0 + 8) * Ndim + cc) = pack_bf2(h0, h1);
                *(uint32_t*)(Clu + (size_t)(r0 + 8) * Ndim + cc) = pack_bf2(l0, l1);
            }
        }
    }
}

// ---------------------------------------------------------------------------
// Attention: split-bf16 HMMA flash kernel (output now fp32 AO)
// ---------------------------------------------------------------------------
#define AT_TILE 16384
#define AT_SMEM (6 * AT_TILE)

__device__ __forceinline__ void stage_qkv(uint32_t dst, const __nv_bfloat16* __restrict__ g,
                                          int t)
{
#pragma unroll
    for (int j = 0; j < 8; j++) {
        int id = t + 128 * j;
        int sub = id >> 9;
        int r = (id >> 3) & 63;
        int u = id & 7;
        uint32_t off = (uint32_t)(r * 128 + u * 16);
        off ^= (off >> 3) & 0x70;
        CP_ASYNC16(dst + sub * 8192 + off, g + (size_t)r * D_MODEL + sub * 64 + u * 8);
    }
}

__global__ __launch_bounds__(128)
void attn_mma(const __nv_bfloat16* __restrict__ Qh, const __nv_bfloat16* __restrict__ Ql,
              const __nv_bfloat16* __restrict__ Kh, const __nv_bfloat16* __restrict__ Kl,
              const __nv_bfloat16* __restrict__ Vh, const __nv_bfloat16* __restrict__ Vl,
              float* __restrict__ AO)
{
    extern __shared__ char sma[];
    const uint32_t sb  = smem_u32(sma);
    const uint32_t sQh = sb, sQl = sb + AT_TILE;
    const uint32_t sKh = sb + 2 * AT_TILE, sKl = sb + 3 * AT_TILE;
    const uint32_t sVh = sb + 4 * AT_TILE, sVl = sb + 5 * AT_TILE;

    const int t    = threadIdx.x;
    const int lane = t & 31;
    const int w    = t >> 5;
    const int q0   = blockIdx.x * 64;
    const int h    = blockIdx.y;
    const int b    = blockIdx.z;

    const size_t headoff = (size_t)b * S_LEN * D_MODEL + (size_t)h * HDIM;

    stage_qkv(sQh, Qh + headoff + (size_t)q0 * D_MODEL, t);
    stage_qkv(sQl, Ql + headoff + (size_t)q0 * D_MODEL, t);
    CP_COMMIT();

    const uint32_t mask = (uint32_t)((lane & 7) << 4);
    const uint32_t akx  = (uint32_t)(((lane >> 4) & 1) * 16);
    const uint32_t bkx  = (uint32_t)(((lane >> 3) & 1) * 16);
    const uint32_t arow = (uint32_t)((w * 16 + (lane & 7) + ((lane >> 3) & 1) * 8) * 128);
    uint32_t brow[4];
#pragma unroll
    for (int p = 0; p < 4; p++)
        brow[p] = (uint32_t)((16 * p + (lane & 7) + ((lane >> 4) & 1) * 8) * 128);
    const uint32_t vkey = (uint32_t)(lane & 15);
    const uint32_t vd8  = (lane & 16) ? 16u : 0u;

    const int qg0 = q0 + w * 16 + (lane >> 2);
    const int qg1 = qg0 + 8;

    float oacc[16][4];
#pragma unroll
    for (int nb = 0; nb < 16; nb++)
#pragma unroll
        for (int i = 0; i < 4; i++) oacc[nb][i] = 0.0f;

    float m0 = -1e30f, m1 = -1e30f, l0 = 0.0f, l1 = 0.0f;
    const float sc2 = 0.12753102833f;   // (1/sqrt(128)) * log2(e)

    for (int c0 = 0; c0 < q0 + 64; c0 += 64) {
        if (!((c0 < PERSIST) || (c0 + 63 >= q0 - (WINDOW - 1)))) continue;

        __syncthreads();
        stage_qkv(sKh, Kh + headoff + (size_t)c0 * D_MODEL, t);
        stage_qkv(sKl, Kl + headoff + (size_t)c0 * D_MODEL, t);
        stage_qkv(sVh, Vh + headoff + (size_t)c0 * D_MODEL, t);
        stage_qkv(sVl, Vl + headoff + (size_t)c0 * D_MODEL, t);
        CP_COMMIT();
        CP_WAIT0();
        __syncthreads();

        float sc[8][4];
#pragma unroll
        for (int nb = 0; nb < 8; nb++)
#pragma unroll
            for (int i = 0; i < 4; i++) sc[nb][i] = 0.0f;

#pragma unroll
        for (int ks = 0; ks < 8; ks++) {
            const uint32_t sub = (uint32_t)((ks >> 2) * 8192);
            const uint32_t kb  = (uint32_t)((ks & 3) * 32);
            const uint32_t ka  = (kb + akx) ^ mask;
            const uint32_t kB  = (kb + bkx) ^ mask;

            uint32_t ah[4], al[4], bh[8][2], bl[8][2];
            ldsm4(ah, sQh + sub + arow + ka);
            ldsm4(al, sQl + sub + arow + ka);
#pragma unroll
            for (int p = 0; p < 4; p++) {
                uint32_t r[4];
                ldsm4(r, sKh + sub + brow[p] + kB);
                bh[2 * p][0] = r[0]; bh[2 * p][1] = r[1];
                bh[2 * p + 1][0] = r[2]; bh[2 * p + 1][1] = r[3];
                ldsm4(r, sKl + sub + brow[p] + kB);
                bl[2 * p][0] = r[0]; bl[2 * p][1] = r[1];
                bl[2 * p + 1][0] = r[2]; bl[2 * p + 1][1] = r[3];
            }
#pragma unroll
            for (int nb = 0; nb < 8; nb++) {
                mma16816(sc[nb], ah, bh[nb]);
                mma16816(sc[nb], ah, bl[nb]);
                mma16816(sc[nb], al, bh[nb]);
            }
        }

        float mx0 = -1e30f, mx1 = -1e30f;
#pragma unroll
        for (int nb = 0; nb < 8; nb++) {
            const int k0 = c0 + nb * 8 + (lane & 3) * 2;
            const int k1 = k0 + 1;
            bool v00 = (k0 <= qg0) && ((qg0 - k0 < WINDOW) || (k0 < PERSIST));
            bool v01 = (k1 <= qg0) && ((qg0 - k1 < WINDOW) || (k1 < PERSIST));
            bool v10 = (k0 <= qg1) && ((qg1 - k0 < WINDOW) || (k0 < PERSIST));
            bool v11 = (k1 <= qg1) && ((qg1 - k1 < WINDOW) || (k1 < PERSIST));
            sc[nb][0] = v00 ? sc[nb][0] * sc2 : -1e30f;
            sc[nb][1] = v01 ? sc[nb][1] * sc2 : -1e30f;
            sc[nb][2] = v10 ? sc[nb][2] * sc2 : -1e30f;
            sc[nb][3] = v11 ? sc[nb][3] * sc2 : -1e30f;
            mx0 = fmaxf(mx0, fmaxf(sc[nb][0], sc[nb][1]));
            mx1 = fmaxf(mx1, fmaxf(sc[nb][2], sc[nb][3]));
        }
        mx0 = fmaxf(mx0, __shfl_xor_sync(0xffffffffu, mx0, 1));
        mx0 = fmaxf(mx0, __shfl_xor_sync(0xffffffffu, mx0, 2));
        mx1 = fmaxf(mx1, __shfl_xor_sync(0xffffffffu, mx1, 1));
        mx1 = fmaxf(mx1, __shfl_xor_sync(0xffffffffu, mx1, 2));

        const float mn0 = fmaxf(m0, mx0), mn1 = fmaxf(m1, mx1);
        const float f0 = exp2f(m0 - mn0), f1 = exp2f(m1 - mn1);
        m0 = mn0; m1 = mn1;
        l0 *= f0; l1 *= f1;
#pragma unroll
        for (int nb = 0; nb < 16; nb++) {
            oacc[nb][0] *= f0; oacc[nb][1] *= f0;
            oacc[nb][2] *= f1; oacc[nb][3] *= f1;
        }

        uint32_t pah[4][4], pal[4][4];
        float ps0 = 0.0f, ps1 = 0.0f;
#pragma unroll
        for (int nb = 0; nb < 8; nb++) {
            float p0 = exp2f(sc[nb][0] - mn0);
            float p1 = exp2f(sc[nb][1] - mn0);
            float p2 = exp2f(sc[nb][2] - mn1);
            float p3 = exp2f(sc[nb][3] - mn1);
            ps0 += p0 + p1; ps1 += p2 + p3;
            float h0, e0, h1, e1, h2, e2, h3, e3;
            split1(p0, h0, e0); split1(p1, h1, e1);
            split1(p2, h2, e2); split1(p3, h3, e3);
            const int kb = nb >> 1, half = (nb & 1) * 2;
            pah[kb][half + 0] = pack_bf2(h0, h1);
            pah[kb][half + 1] = pack_bf2(h2, h3);
            pal[kb][half + 0] = pack_bf2(e0, e1);
            pal[kb][half + 1] = pack_bf2(e2, e3);
        }
        ps0 += __shfl_xor_sync(0xffffffffu, ps0, 1);
        ps0 += __shfl_xor_sync(0xffffffffu, ps0, 2);
        ps1 += __shfl_xor_sync(0xffffffffu, ps1, 1);
        ps1 += __shfl_xor_sync(0xffffffffu, ps1, 2);
        l0 += ps0; l1 += ps1;

#pragma unroll
        for (int kb = 0; kb < 4; kb++) {
            const uint32_t keyrow = (uint32_t)((kb * 16 + vkey) * 128);
#pragma unroll
            for (int g = 0; g < 8; g++) {
                const uint32_t sub = (uint32_t)((g >> 2) * 8192);
                uint32_t off = keyrow + (uint32_t)((g & 3) * 32) + vd8;
                off ^= (off >> 3) & 0x70;
                uint32_t rh[4], rl[4];
                ldsm4t(rh, sVh + sub + off);
                ldsm4t(rl, sVl + sub + off);
                uint32_t bvh0[2] = {rh[0], rh[1]}, bvh1[2] = {rh[2], rh[3]};
                uint32_t bvl0[2] = {rl[0], rl[1]}, bvl1[2] = {rl[2], rl[3]};
                mma16816(oacc[2 * g],     pah[kb], bvh0);
                mma16816(oacc[2 * g],     pah[kb], bvl0);
                mma16816(oacc[2 * g],     pal[kb], bvh0);
                mma16816(oacc[2 * g + 1], pah[kb], bvh1);
                mma16816(oacc[2 * g + 1], pah[kb], bvl1);
                mma16816(oacc[2 * g + 1], pal[kb], bvh1);
            }
        }
    }

    const float inv0 = 1.0f / l0, inv1 = 1.0f / l1;
    const size_t row0 = (size_t)b * S_LEN + (size_t)qg0;
    const size_t row1 = row0 + 8;
#pragma unroll
    for (int nb = 0; nb < 16; nb++) {
        const int d = nb * 8 + (lane & 3) * 2;
        *(float2*)(AO + row0 * D_MODEL + h * HDIM + d) =
            make_float2(oacc[nb][0] * inv0, oacc[nb][1] * inv0);
        *(float2*)(AO + row1 * D_MODEL + h * HDIM + d) =
            make_float2(oacc[nb][2] * inv1, oacc[nb][3] * inv1);
    }
}

// ---------------------------------------------------------------------------
// Launch. Order: [0] weight quant, [1] x quant, [2] Q gemm, [3] KV gemm,
// [4] KV quant, [5] K/V dual gemm (ncu slot), [6] attention, [7] AO quant,
// [8] out gemm.
// ---------------------------------------------------------------------------
extern "C" void kernel_launch(void* const* d_in, const int* in_sizes, int n_in,
                              void* d_out, int out_size)
{
    const float* x   = (const float*)d_in[0];
    const float* Wq  = (const float*)d_in[1];
    const float* Wkv = (const float*)d_in[2];
    const float* Wk  = (const float*)d_in[3];
    const float* Wv  = (const float*)d_in[4];
    const float* Wo  = (const float*)d_in[5];
    float* out = (float*)d_out;

    int8_t *xq1, *xq2, *kvq1, *kvq2, *aoq1, *aoq2;
    int8_t *Wqt1, *Wqt2, *Wkvt1, *Wkvt2, *Wkt1, *Wkt2, *Wvt1, *Wvt2, *Wot1, *Wot2;
    float *sx, *skv, *sao, *sWq, *sWkv, *sWk, *sWv, *sWo, *KVb, *AOb;
    __nv_bfloat16 *Qh, *Ql, *Kh, *Kl, *Vh, *Vl;

    cudaGetSymbolAddress((void**)&xq1,  g_xq1);  cudaGetSymbolAddress((void**)&xq2,  g_xq2);
    cudaGetSymbolAddress((void**)&kvq1, g_kvq1); cudaGetSymbolAddress((void**)&kvq2, g_kvq2);
    cudaGetSymbolAddress((void**)&aoq1, g_aoq1); cudaGetSymbolAddress((void**)&aoq2, g_aoq2);
    cudaGetSymbolAddress((void**)&Wqt1, g_Wqt1); cudaGetSymbolAddress((void**)&Wqt2, g_Wqt2);
    cudaGetSymbolAddress((void**)&Wkvt1, g_Wkvt1); cudaGetSymbolAddress((void**)&Wkvt2, g_Wkvt2);
    cudaGetSymbolAddress((void**)&Wkt1, g_Wkt1); cudaGetSymbolAddress((void**)&Wkt2, g_Wkt2);
    cudaGetSymbolAddress((void**)&Wvt1, g_Wvt1); cudaGetSymbolAddress((void**)&Wvt2, g_Wvt2);
    cudaGetSymbolAddress((void**)&Wot1, g_Wot1); cudaGetSymbolAddress((void**)&Wot2, g_Wot2);
    cudaGetSymbolAddress((void**)&sx,  g_sx);   cudaGetSymbolAddress((void**)&skv, g_skv);
    cudaGetSymbolAddress((void**)&sao, g_sao);
    cudaGetSymbolAddress((void**)&sWq, g_sWq);  cudaGetSymbolAddress((void**)&sWkv, g_sWkv);
    cudaGetSymbolAddress((void**)&sWk, g_sWk);  cudaGetSymbolAddress((void**)&sWv, g_sWv);
    cudaGetSymbolAddress((void**)&sWo, g_sWo);
    cudaGetSymbolAddress((void**)&KVb, g_KV);   cudaGetSymbolAddress((void**)&AOb, g_AO);
    cudaGetSymbolAddress((void**)&Qh, g_Qh);    cudaGetSymbolAddress((void**)&Ql, g_Ql);
    cudaGetSymbolAddress((void**)&Kh, g_Kh);    cudaGetSymbolAddress((void**)&Kl, g_Kl);
    cudaGetSymbolAddress((void**)&Vh, g_Vh);    cudaGetSymbolAddress((void**)&Vl, g_Vl);

    cudaFuncSetAttribute((const void*)gemm_i8<0, 0>,
                         cudaFuncAttributeMaxDynamicSharedMemorySize, GI_SMEM);
    cudaFuncSetAttribute((const void*)gemm_i8<1, 0>,
                         cudaFuncAttributeMaxDynamicSharedMemorySize, GI_SMEM);
    cudaFuncSetAttribute((const void*)gemm_i8<1, 1>,
                         cudaFuncAttributeMaxDynamicSharedMemorySize, GI_SMEM);
    cudaFuncSetAttribute((const void*)attn_mma,
                         cudaFuncAttributeMaxDynamicSharedMemorySize, AT_SMEM);

    // [0] weight quantization (all 5 matrices, transposed 2-slice int8)
    quant_weights<<<272, dim3(32, 8)>>>(Wq, Wkv, Wk, Wv, Wo);
    // [1] x row quantization
    quant_rows<<<M_ROWS, 256>>>(x, D_MODEL, xq1, xq2, sx);
    // [2] Q = x @ Wq   (split-bf16 out)
    gemm_i8<1, 0><<<dim3(D_MODEL / 64, M_ROWS / 128), 256, GI_SMEM>>>(
        xq1, xq2, sx, Wqt1, Wqt2, sWq, nullptr, Qh, Ql,
        nullptr, nullptr, nullptr, nullptr, nullptr, nullptr,
        D_MODEL, 0, D_MODEL, 0);
    // [3] KV = x @ Wkv (fp32 out)
    gemm_i8<0, 0><<<dim3(L_LAT / 64, M_ROWS / 128), 256, GI_SMEM>>>(
        xq1, xq2, sx, Wkvt1, Wkvt2, sWkv, KVb, nullptr, nullptr,
        nullptr, nullptr, nullptr, nullptr, nullptr, nullptr,
        L_LAT, 0, D_MODEL, 0);
    // [4] KV row quantization
    quant_rows<<<M_ROWS, 256>>>(KVb, L_LAT, kvq1, kvq2, skv);
    // [5] K,V = KV @ {Wk, Wv}  (dual, split-bf16 out)   <-- ncu capture slot
    gemm_i8<1, 1><<<dim3(2 * D_MODEL / 64, M_ROWS / 128), 256, GI_SMEM>>>(
        kvq1, kvq2, skv, Wkt1, Wkt2, sWk, nullptr, Kh, Kl,
        Wvt1, Wvt2, sWv, nullptr, Vh, Vl,
        D_MODEL, D_MODEL, L_LAT, D_MODEL / 64);
    // [6] attention -> fp32 AO
    attn_mma<<<dim3(S_LEN / 64, NHEADS, BATCH), 128, AT_SMEM>>>(
        Qh, Ql, Kh, Kl, Vh, Vl, AOb);
    // [7] AO row quantization
    quant_rows<<<M_ROWS, 256>>>(AOb, D_MODEL, aoq1, aoq2, sao);
    // [8] out = AO @ Wo (fp32 out)
    gemm_i8<0, 0><<<dim3(D_MODEL / 64, M_ROWS / 128), 256, GI_SMEM>>>(
        aoq1, aoq2, sao, Wot1, Wot2, sWo, out, nullptr, nullptr,
        nullptr, nullptr, nullptr, nullptr, nullptr, nullptr,
        D_MODEL, 0, D_MODEL, 0);
}

// round 12
// speedup vs baseline: 2.8605x; 2.8605x over previous
#include <cuda_runtime.h>
#include <cuda_bf16.h>
#include <cstdint>
#include <math.h>

// ---------------------------------------------------------------------------
// Problem constants
// ---------------------------------------------------------------------------
#define S_LEN   2048
#define D_MODEL 2048
#define L_LAT   512
#define BATCH   2
#define NHEADS  16
#define HDIM    128
#define M_ROWS  (BATCH * S_LEN)   // 4096
#define WINDOW  128
#define PERSIST 16

// ---------------------------------------------------------------------------
// PTX helpers
// ---------------------------------------------------------------------------
__device__ __forceinline__ uint32_t smem_u32(const void* p) {
    uint32_t a;
    asm("{ .reg .u64 t; cvta.to.shared.u64 t, %1; cvt.u32.u64 %0, t; }"
        : "=r"(a) : "l"(p));
    return a;
}

__device__ __forceinline__ void ldsm4(uint32_t* r, uint32_t addr) {
    asm volatile("ldmatrix.sync.aligned.m8n8.x4.shared.b16 {%0,%1,%2,%3}, [%4];"
                 : "=r"(r[0]), "=r"(r[1]), "=r"(r[2]), "=r"(r[3]) : "r"(addr));
}
__device__ __forceinline__ void ldsm4t(uint32_t* r, uint32_t addr) {
    asm volatile("ldmatrix.sync.aligned.m8n8.x4.trans.shared.b16 {%0,%1,%2,%3}, [%4];"
                 : "=r"(r[0]), "=r"(r[1]), "=r"(r[2]), "=r"(r[3]) : "r"(addr));
}

__device__ __forceinline__ void mma16816(float* c, const uint32_t* a, const uint32_t* b) {
    asm volatile("mma.sync.aligned.m16n8k16.row.col.f32.bf16.bf16.f32 "
                 "{%0,%1,%2,%3}, {%4,%5,%6,%7}, {%8,%9}, {%0,%1,%2,%3};"
                 : "+f"(c[0]), "+f"(c[1]), "+f"(c[2]), "+f"(c[3])
                 : "r"(a[0]), "r"(a[1]), "r"(a[2]), "r"(a[3]),
                   "r"(b[0]), "r"(b[1]));
}

#define CP_ASYNC16(s, g) \
    asm volatile("cp.async.cg.shared.global [%0], [%1], 16;" :: "r"(s), "l"(g))
#define CP_COMMIT() asm volatile("cp.async.commit_group;" ::: "memory")
#define CP_WAIT0()  asm volatile("cp.async.wait_group 0;" ::: "memory")
#define CP_WAIT1()  asm volatile("cp.async.wait_group 1;" ::: "memory")

__device__ __forceinline__ uint32_t pack_bf2(float a, float b) {
    __nv_bfloat162 v = __halves2bfloat162(__float2bfloat16(a), __float2bfloat16(b));
    return *(uint32_t*)&v;
}
__device__ __forceinline__ void split1(float v, float& hi_f, float& lo_f) {
    __nv_bfloat16 h = __float2bfloat16(v);
    hi_f = __bfloat162float(h);
    lo_f = v - hi_f;
}

// ---------------------------------------------------------------------------
// Scratch buffers
// ---------------------------------------------------------------------------
#define N_XD   ((size_t)M_ROWS * D_MODEL)
#define N_DD   ((size_t)D_MODEL * D_MODEL)
#define N_DL   ((size_t)D_MODEL * L_LAT)
#define N_ML   ((size_t)M_ROWS * L_LAT)

__device__ __nv_bfloat16 g_xh [N_XD];
__device__ __nv_bfloat16 g_xl [N_XD];
__device__ __nv_bfloat16 g_Wqh[N_DD];
__device__ __nv_bfloat16 g_Wql[N_DD];
__device__ __nv_bfloat16 g_Wkvh[N_DL];
__device__ __nv_bfloat16 g_Wkvl[N_DL];
__device__ __nv_bfloat16 g_Wkh[N_DL];
__device__ __nv_bfloat16 g_Wkl[N_DL];
__device__ __nv_bfloat16 g_Wvh[N_DL];
__device__ __nv_bfloat16 g_Wvl[N_DL];
__device__ __nv_bfloat16 g_Woh[N_DD];
__device__ __nv_bfloat16 g_Wol[N_DD];
__device__ __nv_bfloat16 g_KVh[N_ML];
__device__ __nv_bfloat16 g_KVl[N_ML];
__device__ __nv_bfloat16 g_Qh[N_XD];
__device__ __nv_bfloat16 g_Ql[N_XD];
__device__ __nv_bfloat16 g_Kh[N_XD];
__device__ __nv_bfloat16 g_Kl[N_XD];
__device__ __nv_bfloat16 g_Vh[N_XD];
__device__ __nv_bfloat16 g_Vl[N_XD];
__device__ __nv_bfloat16 g_AOh[N_XD];
__device__ __nv_bfloat16 g_AOl[N_XD];

// ---------------------------------------------------------------------------
// fp32 -> bf16 hi/lo split kernels
// ---------------------------------------------------------------------------
__device__ __forceinline__ void split4_store(float4 v, __nv_bfloat162* oh,
                                             __nv_bfloat162* ol, size_t i2)
{
    float h0, l0, h1, l1, h2, l2, h3, l3;
    split1(v.x, h0, l0); split1(v.y, h1, l1);
    split1(v.z, h2, l2); split1(v.w, h3, l3);
    oh[i2]     = __halves2bfloat162(__float2bfloat16(h0), __float2bfloat16(h1));
    oh[i2 + 1] = __halves2bfloat162(__float2bfloat16(h2), __float2bfloat16(h3));
    ol[i2]     = __halves2bfloat162(__float2bfloat16(l0), __float2bfloat16(l1));
    ol[i2 + 1] = __halves2bfloat162(__float2bfloat16(l2), __float2bfloat16(l3));
}

__global__ void split_rows(const float4* __restrict__ in,
                           __nv_bfloat162* __restrict__ oh,
                           __nv_bfloat162* __restrict__ ol, int n4)
{
    int i = blockIdx.x * blockDim.x + threadIdx.x;
    if (i >= n4) return;
    split4_store(in[i], oh, ol, (size_t)2 * i);
}

// merged split for 5 weight matrices (Wq | Wkv | Wk | Wv | Wo)
__global__ void split_weights(const float4* __restrict__ Wq,  const float4* __restrict__ Wkv,
                              const float4* __restrict__ Wk,  const float4* __restrict__ Wv,
                              const float4* __restrict__ Wo,
                              __nv_bfloat162* __restrict__ Wqh,  __nv_bfloat162* __restrict__ Wql,
                              __nv_bfloat162* __restrict__ Wkvh, __nv_bfloat162* __restrict__ Wkvl,
                              __nv_bfloat162* __restrict__ Wkh,  __nv_bfloat162* __restrict__ Wkl,
                              __nv_bfloat162* __restrict__ Wvh,  __nv_bfloat162* __restrict__ Wvl,
                              __nv_bfloat162* __restrict__ Woh,  __nv_bfloat162* __restrict__ Wol)
{
    const int S0 = (int)(N_DD / 4);
    const int SL = (int)(N_DL / 4);
    int i = blockIdx.x * blockDim.x + threadIdx.x;
    if (i < S0) { split4_store(Wq[i], Wqh, Wql, (size_t)2 * i); return; }
    i -= S0;
    if (i < SL) { split4_store(Wkv[i], Wkvh, Wkvl, (size_t)2 * i); return; }
    i -= SL;
    if (i < SL) { split4_store(Wk[i], Wkh, Wkl, (size_t)2 * i); return; }
    i -= SL;
    if (i < SL) { split4_store(Wv[i], Wvh, Wvl, (size_t)2 * i); return; }
    i -= SL;
    if (i < S0) { split4_store(Wo[i], Woh, Wol, (size_t)2 * i); return; }
}

// ---------------------------------------------------------------------------
// HMMA split-bf16 GEMM. Block 128x64, BK=64, 128 threads = 4 warps
// (warp tile 64x32, 2M x 2N -> 2x fragment reuse vs 32x32; LDSM traffic -25%,
// since L1/smem port was co-binding with the tensor pipe at R9).
// 2-stage cp.async, 96 KB smem -> 2 CTAs/SM (sync bubbles covered cross-CTA).
// B K-major via ldmatrix.trans.
// MODE 0: fp32 C. MODE 1: split bf16 (Ch, Cl).
// DUAL 1: blocks with bx >= nx1 run the second GEMM (B2/C2, N2dim).
// ---------------------------------------------------------------------------
#define GT_A_BYTES  (128 * 64 * 2)     // 16 KB
#define GT_B_BYTES  (64 * 64 * 2)      //  8 KB
#define GSTAGE      (2 * GT_A_BYTES + 2 * GT_B_BYTES)  // 48 KB
#define GSMEM_TOTAL (2 * GSTAGE)                        // 96 KB

// A tile: 128 M-rows x 64 K-cols (128 B rows), SW128 swizzle, 128 threads
__device__ __forceinline__ void stage_a(uint32_t sdst,
                                        const __nv_bfloat16* __restrict__ g,
                                        int ldK, int t)
{
#pragma unroll
    for (int j = 0; j < 8; j++) {
        int id = t + 128 * j;          // 0..1023
        int r = id >> 3, c = id & 7;
        uint32_t off = (uint32_t)(r * 128 + c * 16);
        off ^= (off >> 3) & 0x70;
        CP_ASYNC16(sdst + off, g + (size_t)r * ldK + c * 8);
    }
}

// B tile: 64 K-rows x 64 N-cols (128 B rows), SW128 swizzle, 128 threads
__device__ __forceinline__ void stage_b(uint32_t sdst,
                                        const __nv_bfloat16* __restrict__ g,
                                        int ldN, int t)
{
#pragma unroll
    for (int j = 0; j < 4; j++) {
        int id = t + 128 * j;          // 0..511
        int r = id >> 3;               // 0..63
        int u = id & 7;
        uint32_t off = (uint32_t)(r * 128 + u * 16);
        off ^= (off >> 3) & 0x70;
        CP_ASYNC16(sdst + off, g + (size_t)r * ldN + u * 8);
    }
}

template <int MODE, int DUAL>
__global__ __launch_bounds__(128, 2)
void gemm_mma(const __nv_bfloat16* __restrict__ Ah, const __nv_bfloat16* __restrict__ Al,
              const __nv_bfloat16* __restrict__ Bh, const __nv_bfloat16* __restrict__ Bl,
              float* __restrict__ C, __nv_bfloat16* __restrict__ Ch,
              __nv_bfloat16* __restrict__ Cl,
              const __nv_bfloat16* __restrict__ B2h, const __nv_bfloat16* __restrict__ B2l,
              __nv_bfloat16* __restrict__ C2h, __nv_bfloat16* __restrict__ C2l,
              int N1dim, int N2dim, int Kdim, int nx1)
{
    extern __shared__ char smc[];
    const uint32_t sb = smem_u32(smc);
    const int t    = threadIdx.x;
    const int lane = t & 31;
    const int w    = t >> 5;           // 0..3

    int bx = blockIdx.x;
    int Ndim = N1dim;
    const __nv_bfloat16* Bhu = Bh;
    const __nv_bfloat16* Blu = Bl;
    __nv_bfloat16* Chu = Ch;
    __nv_bfloat16* Clu = Cl;
    if (DUAL) {
        if (bx >= nx1) {
            bx -= nx1; Ndim = N2dim;
            Bhu = B2h; Blu = B2l; Chu = C2h; Clu = C2l;
        }
    }

    const int bm = blockIdx.y * 128;
    const int bn = bx * 64;
    const int m0 = (w >> 1) * 64;      // 0, 64
    const int n0 = (w & 1) * 32;       // 0, 32

    const __nv_bfloat16* Ahp = Ah + (size_t)bm * Kdim;
    const __nv_bfloat16* Alp = Al + (size_t)bm * Kdim;
    const __nv_bfloat16* Bhp = Bhu + bn;
    const __nv_bfloat16* Blp = Blu + bn;

    // A ldmatrix geometry
    const uint32_t mask = (uint32_t)((lane & 7) << 4);
    const uint32_t akx  = (uint32_t)(((lane >> 4) & 1) * 16);
    uint32_t arow[4];
#pragma unroll
    for (int mt = 0; mt < 4; mt++)
        arow[mt] = (uint32_t)((m0 + 16 * mt + (lane & 7) + ((lane >> 3) & 1) * 8) * 128);
    // B trans-ldmatrix geometry (warp owns n0..n0+31 of the 64-col tile)
    const uint32_t vkey  = (uint32_t)(lane & 15);
    const uint32_t vd8   = (lane & 16) ? 16u : 0u;
    const uint32_t nbyte = (uint32_t)(n0 * 2);

    float acc[4][4][4];
#pragma unroll
    for (int mt = 0; mt < 4; mt++)
#pragma unroll
        for (int nt = 0; nt < 4; nt++)
#pragma unroll
            for (int i = 0; i < 4; i++) acc[mt][nt][i] = 0.0f;

    const int nch = Kdim >> 6;

    // prologue: stage chunk 0 -> stage 0
    stage_a(sb + 0,                          Ahp, Kdim, t);
    stage_a(sb + GT_A_BYTES,                 Alp, Kdim, t);
    stage_b(sb + 2 * GT_A_BYTES,             Bhp, Ndim, t);
    stage_b(sb + 2 * GT_A_BYTES + GT_B_BYTES, Blp, Ndim, t);
    CP_COMMIT();

    int stg = 0;
    for (int c = 0; c < nch; ++c) {
        if (c + 1 < nch) {
            uint32_t nb = sb + (uint32_t)((stg ^ 1) * GSTAGE);
            size_t ko = (size_t)(c + 1) * 64;
            stage_a(nb + 0,                          Ahp + ko, Kdim, t);
            stage_a(nb + GT_A_BYTES,                 Alp + ko, Kdim, t);
            stage_b(nb + 2 * GT_A_BYTES,             Bhp + ko * Ndim, Ndim, t);
            stage_b(nb + 2 * GT_A_BYTES + GT_B_BYTES, Blp + ko * Ndim, Ndim, t);
            CP_COMMIT();
            CP_WAIT1();
        } else {
            CP_WAIT0();
        }
        __syncthreads();

        const uint32_t base = sb + (uint32_t)(stg * GSTAGE);
        const uint32_t sAh = base;
        const uint32_t sAl = base + GT_A_BYTES;
        const uint32_t sBh = base + 2 * GT_A_BYTES;
        const uint32_t sBl = base + 2 * GT_A_BYTES + GT_B_BYTES;

#pragma unroll
        for (int s = 0; s < 4; s++) {
            const uint32_t ka = ((uint32_t)(32 * s) + akx) ^ mask;

            uint32_t ah[4][4], al[4][4], bh[4][2], bl[4][2];
#pragma unroll
            for (int mt = 0; mt < 4; mt++) {
                ldsm4(ah[mt], sAh + arow[mt] + ka);
                ldsm4(al[mt], sAl + arow[mt] + ka);
            }
#pragma unroll
            for (int p = 0; p < 2; p++) {
                uint32_t off = (uint32_t)((s * 16 + vkey) * 128) + nbyte
                             + (uint32_t)(p * 32) + vd8;
                off ^= (off >> 3) & 0x70;
                uint32_t r[4];
                ldsm4t(r, sBh + off);
                bh[2 * p][0] = r[0]; bh[2 * p][1] = r[1];
                bh[2 * p + 1][0] = r[2]; bh[2 * p + 1][1] = r[3];
                ldsm4t(r, sBl + off);
                bl[2 * p][0] = r[0]; bl[2 * p][1] = r[1];
                bl[2 * p + 1][0] = r[2]; bl[2 * p + 1][1] = r[3];
            }
            // term-major passes: long independent chains
#pragma unroll
            for (int mt = 0; mt < 4; mt++)
#pragma unroll
                for (int nt = 0; nt < 4; nt++)
                    mma16816(acc[mt][nt], ah[mt], bh[nt]);
#pragma unroll
            for (int mt = 0; mt < 4; mt++)
#pragma unroll
                for (int nt = 0; nt < 4; nt++)
                    mma16816(acc[mt][nt], ah[mt], bl[nt]);
#pragma unroll
            for (int mt = 0; mt < 4; mt++)
#pragma unroll
                for (int nt = 0; nt < 4; nt++)
                    mma16816(acc[mt][nt], al[mt], bh[nt]);
        }
        __syncthreads();   // all warps done with stage before re-staging it
        stg ^= 1;
    }

    const int rbase = bm + m0 + (lane >> 2);
    const int cbase = bn + n0 + (lane & 3) * 2;
#pragma unroll
    for (int mt = 0; mt < 4; mt++)
#pragma unroll
        for (int nt = 0; nt < 4; nt++) {
            const int r0 = rbase + 16 * mt;
            const int cc = cbase + 8 * nt;
            if (MODE == 0) {
                float* p0 = C + (size_t)r0 * Ndim + cc;
                float* p1 = p0 + (size_t)8 * Ndim;
                *(float2*)p0 = make_float2(acc[mt][nt][0], acc[mt][nt][1]);
                *(float2*)p1 = make_float2(acc[mt][nt][2], acc[mt][nt][3]);
            } else {
                float h0, l0, h1, l1;
                split1(acc[mt][nt][0], h0, l0); split1(acc[mt][nt][1], h1, l1);
                *(uint32_t*)(Chu + (size_t)r0 * Ndim + cc) = pack_bf2(h0, h1);
                *(uint32_t*)(Clu + (size_t)r0 * Ndim + cc) = pack_bf2(l0, l1);
                split1(acc[mt][nt][2], h0, l0); split1(acc[mt][nt][3], h1, l1);
                *(uint32_t*)(Chu + (size_t)(r0 + 8) * Ndim + cc) = pack_bf2(h0, h1);
                *(uint32_t*)(Clu + (size_t)(r0 + 8) * Ndim + cc) = pack_bf2(l0, l1);
            }
        }
}

// ---------------------------------------------------------------------------
// Attention: split-bf16 HMMA flash kernel (unchanged from R9)
// ---------------------------------------------------------------------------
#define AT_TILE 16384
#define AT_SMEM (6 * AT_TILE)

__device__ __forceinline__ void stage_qkv(uint32_t dst, const __nv_bfloat16* __restrict__ g,
                                          int t)
{
#pragma unroll
    for (int j = 0; j < 8; j++) {
        int id = t + 128 * j;
        int sub = id >> 9;
        int r = (id >> 3) & 63;
        int u = id & 7;
        uint32_t off = (uint32_t)(r * 128 + u * 16);
        off ^= (off >> 3) & 0x70;
        CP_ASYNC16(dst + sub * 8192 + off, g + (size_t)r * D_MODEL + sub * 64 + u * 8);
    }
}

__global__ __launch_bounds__(128)
void attn_mma(const __nv_bfloat16* __restrict__ Qh, const __nv_bfloat16* __restrict__ Ql,
              const __nv_bfloat16* __restrict__ Kh, const __nv_bfloat16* __restrict__ Kl,
              const __nv_bfloat16* __restrict__ Vh, const __nv_bfloat16* __restrict__ Vl,
              __nv_bfloat16* __restrict__ AOh, __nv_bfloat16* __restrict__ AOl)
{
    extern __shared__ char sma[];
    const uint32_t sb  = smem_u32(sma);
    const uint32_t sQh = sb, sQl = sb + AT_TILE;
    const uint32_t sKh = sb + 2 * AT_TILE, sKl = sb + 3 * AT_TILE;
    const uint32_t sVh = sb + 4 * AT_TILE, sVl = sb + 5 * AT_TILE;

    const int t    = threadIdx.x;
    const int lane = t & 31;
    const int w    = t >> 5;
    const int q0   = blockIdx.x * 64;
    const int h    = blockIdx.y;
    const int b    = blockIdx.z;

    const size_t headoff = (size_t)b * S_LEN * D_MODEL + (size_t)h * HDIM;

    stage_qkv(sQh, Qh + headoff + (size_t)q0 * D_MODEL, t);
    stage_qkv(sQl, Ql + headoff + (size_t)q0 * D_MODEL, t);
    CP_COMMIT();

    const uint32_t mask = (uint32_t)((lane & 7) << 4);
    const uint32_t akx  = (uint32_t)(((lane >> 4) & 1) * 16);
    const uint32_t bkx  = (uint32_t)(((lane >> 3) & 1) * 16);
    const uint32_t arow = (uint32_t)((w * 16 + (lane & 7) + ((lane >> 3) & 1) * 8) * 128);
    uint32_t brow[4];
#pragma unroll
    for (int p = 0; p < 4; p++)
        brow[p] = (uint32_t)((16 * p + (lane & 7) + ((lane >> 4) & 1) * 8) * 128);
    const uint32_t vkey = (uint32_t)(lane & 15);
    const uint32_t vd8  = (lane & 16) ? 16u : 0u;

    const int qg0 = q0 + w * 16 + (lane >> 2);
    const int qg1 = qg0 + 8;

    float oacc[16][4];
#pragma unroll
    for (int nb = 0; nb < 16; nb++)
#pragma unroll
        for (int i = 0; i < 4; i++) oacc[nb][i] = 0.0f;

    float m0 = -1e30f, m1 = -1e30f, l0 = 0.0f, l1 = 0.0f;
    const float sc2 = 0.12753102833f;   // (1/sqrt(128)) * log2(e)

    for (int c0 = 0; c0 < q0 + 64; c0 += 64) {
        if (!((c0 < PERSIST) || (c0 + 63 >= q0 - (WINDOW - 1)))) continue;

        __syncthreads();
        stage_qkv(sKh, Kh + headoff + (size_t)c0 * D_MODEL, t);
        stage_qkv(sKl, Kl + headoff + (size_t)c0 * D_MODEL, t);
        stage_qkv(sVh, Vh + headoff + (size_t)c0 * D_MODEL, t);
        stage_qkv(sVl, Vl + headoff + (size_t)c0 * D_MODEL, t);
        CP_COMMIT();
        CP_WAIT0();
        __syncthreads();

        float sc[8][4];
#pragma unroll
        for (int nb = 0; nb < 8; nb++)
#pragma unroll
            for (int i = 0; i < 4; i++) sc[nb][i] = 0.0f;

#pragma unroll
        for (int ks = 0; ks < 8; ks++) {
            const uint32_t sub = (uint32_t)((ks >> 2) * 8192);
            const uint32_t kb  = (uint32_t)((ks & 3) * 32);
            const uint32_t ka  = (kb + akx) ^ mask;
            const uint32_t kB  = (kb + bkx) ^ mask;

            uint32_t ah[4], al[4], bh[8][2], bl[8][2];
            ldsm4(ah, sQh + sub + arow + ka);
            ldsm4(al, sQl + sub + arow + ka);
#pragma unroll
            for (int p = 0; p < 4; p++) {
                uint32_t r[4];
                ldsm4(r, sKh + sub + brow[p] + kB);
                bh[2 * p][0] = r[0]; bh[2 * p][1] = r[1];
                bh[2 * p + 1][0] = r[2]; bh[2 * p + 1][1] = r[3];
                ldsm4(r, sKl + sub + brow[p] + kB);
                bl[2 * p][0] = r[0]; bl[2 * p][1] = r[1];
                bl[2 * p + 1][0] = r[2]; bl[2 * p + 1][1] = r[3];
            }
#pragma unroll
            for (int nb = 0; nb < 8; nb++) {
                mma16816(sc[nb], ah, bh[nb]);
                mma16816(sc[nb], ah, bl[nb]);
                mma16816(sc[nb], al, bh[nb]);
            }
        }

        float mx0 = -1e30f, mx1 = -1e30f;
#pragma unroll
        for (int nb = 0; nb < 8; nb++) {
            const int k0 = c0 + nb * 8 + (lane & 3) * 2;
            const int k1 = k0 + 1;
            bool v00 = (k0 <= qg0) && ((qg0 - k0 < WINDOW) || (k0 < PERSIST));
            bool v01 = (k1 <= qg0) && ((qg0 - k1 < WINDOW) || (k1 < PERSIST));
            bool v10 = (k0 <= qg1) && ((qg1 - k0 < WINDOW) || (k0 < PERSIST));
            bool v11 = (k1 <= qg1) && ((qg1 - k1 < WINDOW) || (k1 < PERSIST));
            sc[nb][0] = v00 ? sc[nb][0] * sc2 : -1e30f;
            sc[nb][1] = v01 ? sc[nb][1] * sc2 : -1e30f;
            sc[nb][2] = v10 ? sc[nb][2] * sc2 : -1e30f;
            sc[nb][3] = v11 ? sc[nb][3] * sc2 : -1e30f;
            mx0 = fmaxf(mx0, fmaxf(sc[nb][0], sc[nb][1]));
            mx1 = fmaxf(mx1, fmaxf(sc[nb][2], sc[nb][3]));
        }
        mx0 = fmaxf(mx0, __shfl_xor_sync(0xffffffffu, mx0, 1));
        mx0 = fmaxf(mx0, __shfl_xor_sync(0xffffffffu, mx0, 2));
        mx1 = fmaxf(mx1, __shfl_xor_sync(0xffffffffu, mx1, 1));
        mx1 = fmaxf(mx1, __shfl_xor_sync(0xffffffffu, mx1, 2));

        const float mn0 = fmaxf(m0, mx0), mn1 = fmaxf(m1, mx1);
        const float f0 = exp2f(m0 - mn0), f1 = exp2f(m1 - mn1);
        m0 = mn0; m1 = mn1;
        l0 *= f0; l1 *= f1;
#pragma unroll
        for (int nb = 0; nb < 16; nb++) {
            oacc[nb][0] *= f0; oacc[nb][1] *= f0;
            oacc[nb][2] *= f1; oacc[nb][3] *= f1;
        }

        uint32_t pah[4][4], pal[4][4];
        float ps0 = 0.0f, ps1 = 0.0f;
#pragma unroll
        for (int nb = 0; nb < 8; nb++) {
            float p0 = exp2f(sc[nb][0] - mn0);
            float p1 = exp2f(sc[nb][1] - mn0);
            float p2 = exp2f(sc[nb][2] - mn1);
            float p3 = exp2f(sc[nb][3] - mn1);
            ps0 += p0 + p1; ps1 += p2 + p3;
            float h0, e0, h1, e1, h2, e2, h3, e3;
            split1(p0, h0, e0); split1(p1, h1, e1);
            split1(p2, h2, e2); split1(p3, h3, e3);
            const int kb = nb >> 1, half = (nb & 1) * 2;
            pah[kb][half + 0] = pack_bf2(h0, h1);
            pah[kb][half + 1] = pack_bf2(h2, h3);
            pal[kb][half + 0] = pack_bf2(e0, e1);
            pal[kb][half + 1] = pack_bf2(e2, e3);
        }
        ps0 += __shfl_xor_sync(0xffffffffu, ps0, 1);
        ps0 += __shfl_xor_sync(0xffffffffu, ps0, 2);
        ps1 += __shfl_xor_sync(0xffffffffu, ps1, 1);
        ps1 += __shfl_xor_sync(0xffffffffu, ps1, 2);
        l0 += ps0; l1 += ps1;

#pragma unroll
        for (int kb = 0; kb < 4; kb++) {
            const uint32_t keyrow = (uint32_t)((kb * 16 + vkey) * 128);
#pragma unroll
            for (int g = 0; g < 8; g++) {
                const uint32_t sub = (uint32_t)((g >> 2) * 8192);
                uint32_t off = keyrow + (uint32_t)((g & 3) * 32) + vd8;
                off ^= (off >> 3) & 0x70;
                uint32_t rh[4], rl[4];
                ldsm4t(rh, sVh + sub + off);
                ldsm4t(rl, sVl + sub + off);
                uint32_t bvh0[2] = {rh[0], rh[1]}, bvh1[2] = {rh[2], rh[3]};
                uint32_t bvl0[2] = {rl[0], rl[1]}, bvl1[2] = {rl[2], rl[3]};
                mma16816(oacc[2 * g],     pah[kb], bvh0);
                mma16816(oacc[2 * g],     pah[kb], bvl0);
                mma16816(oacc[2 * g],     pal[kb], bvh0);
                mma16816(oacc[2 * g + 1], pah[kb], bvh1);
                mma16816(oacc[2 * g + 1], pah[kb], bvl1);
                mma16816(oacc[2 * g + 1], pal[kb], bvh1);
            }
        }
    }

    const float inv0 = 1.0f / l0, inv1 = 1.0f / l1;
    const size_t row0 = (size_t)b * S_LEN + (size_t)qg0;
    const size_t row1 = row0 + 8;
#pragma unroll
    for (int nb = 0; nb < 16; nb++) {
        const int d = nb * 8 + (lane & 3) * 2;
        float h0, e0, h1, e1;
        split1(oacc[nb][0] * inv0, h0, e0); split1(oacc[nb][1] * inv0, h1, e1);
        *(uint32_t*)(AOh + row0 * D_MODEL + h * HDIM + d) = pack_bf2(h0, h1);
        *(uint32_t*)(AOl + row0 * D_MODEL + h * HDIM + d) = pack_bf2(e0, e1);
        split1(oacc[nb][2] * inv1, h0, e0); split1(oacc[nb][3] * inv1, h1, e1);
        *(uint32_t*)(AOh + row1 * D_MODEL + h * HDIM + d) = pack_bf2(h0, h1);
        *(uint32_t*)(AOl + row1 * D_MODEL + h * HDIM + d) = pack_bf2(e0, e1);
    }
}

// ---------------------------------------------------------------------------
// Launch. 6 launches; index 5 (ncu -s 5 -c 1) = out GEMM.
// ---------------------------------------------------------------------------
extern "C" void kernel_launch(void* const* d_in, const int* in_sizes, int n_in,
                              void* d_out, int out_size)
{
    const float* x   = (const float*)d_in[0];
    const float* Wq  = (const float*)d_in[1];
    const float* Wkv = (const float*)d_in[2];
    const float* Wk  = (const float*)d_in[3];
    const float* Wv  = (const float*)d_in[4];
    const float* Wo  = (const float*)d_in[5];
    float* out = (float*)d_out;

    __nv_bfloat16 *xh, *xl, *Wqh, *Wql, *Wkvh, *Wkvl, *Wkh, *Wkl,
                  *Wvh, *Wvl, *Woh, *Wol, *KVh, *KVl,
                  *Qh, *Ql, *Kh, *Kl, *Vh, *Vl, *AOh, *AOl;
    cudaGetSymbolAddress((void**)&xh,   g_xh);
    cudaGetSymbolAddress((void**)&xl,   g_xl);
    cudaGetSymbolAddress((void**)&Wqh,  g_Wqh);
    cudaGetSymbolAddress((void**)&Wql,  g_Wql);
    cudaGetSymbolAddress((void**)&Wkvh, g_Wkvh);
    cudaGetSymbolAddress((void**)&Wkvl, g_Wkvl);
    cudaGetSymbolAddress((void**)&Wkh,  g_Wkh);
    cudaGetSymbolAddress((void**)&Wkl,  g_Wkl);
    cudaGetSymbolAddress((void**)&Wvh,  g_Wvh);
    cudaGetSymbolAddress((void**)&Wvl,  g_Wvl);
    cudaGetSymbolAddress((void**)&Woh,  g_Woh);
    cudaGetSymbolAddress((void**)&Wol,  g_Wol);
    cudaGetSymbolAddress((void**)&KVh,  g_KVh);
    cudaGetSymbolAddress((void**)&KVl,  g_KVl);
    cudaGetSymbolAddress((void**)&Qh,   g_Qh);
    cudaGetSymbolAddress((void**)&Ql,   g_Ql);
    cudaGetSymbolAddress((void**)&Kh,   g_Kh);
    cudaGetSymbolAddress((void**)&Kl,   g_Kl);
    cudaGetSymbolAddress((void**)&Vh,   g_Vh);
    cudaGetSymbolAddress((void**)&Vl,   g_Vl);
    cudaGetSymbolAddress((void**)&AOh,  g_AOh);
    cudaGetSymbolAddress((void**)&AOl,  g_AOl);

    cudaFuncSetAttribute((const void*)gemm_mma<0, 0>,
                         cudaFuncAttributeMaxDynamicSharedMemorySize, GSMEM_TOTAL);
    cudaFuncSetAttribute((const void*)gemm_mma<1, 1>,
                         cudaFuncAttributeMaxDynamicSharedMemorySize, GSMEM_TOTAL);
    cudaFuncSetAttribute((const void*)attn_mma,
                         cudaFuncAttributeMaxDynamicSharedMemorySize, AT_SMEM);

    // [0] x split
    split_rows<<<(int)(N_XD / 4 + 255) / 256, 256>>>((const float4*)x,
        (__nv_bfloat162*)xh, (__nv_bfloat162*)xl, (int)(N_XD / 4));
    // [1] merged weight split (Wq | Wkv | Wk | Wv | Wo)
    {
        int n4 = (int)(2 * (N_DD / 4) + 3 * (N_DL / 4));
        split_weights<<<(n4 + 255) / 256, 256>>>(
            (const float4*)Wq, (const float4*)Wkv, (const float4*)Wk,
            (const float4*)Wv, (const float4*)Wo,
            (__nv_bfloat162*)Wqh,  (__nv_bfloat162*)Wql,
            (__nv_bfloat162*)Wkvh, (__nv_bfloat162*)Wkvl,
            (__nv_bfloat162*)Wkh,  (__nv_bfloat162*)Wkl,
            (__nv_bfloat162*)Wvh,  (__nv_bfloat162*)Wvl,
            (__nv_bfloat162*)Woh,  (__nv_bfloat162*)Wol);
    }
    // [2] Q = x @ Wq  and  KV = x @ Wkv  (fused dual; 40x32 blocks)
    gemm_mma<1, 1><<<dim3(D_MODEL / 64 + L_LAT / 64, M_ROWS / 128), 128, GSMEM_TOTAL>>>(
        xh, xl, Wqh, Wql, nullptr, Qh, Ql,
        Wkvh, Wkvl, KVh, KVl, D_MODEL, L_LAT, D_MODEL, D_MODEL / 64);
    // [3] K,V = KV @ {Wk, Wv}  (dual; 64x32 blocks)
    gemm_mma<1, 1><<<dim3(2 * D_MODEL / 64, M_ROWS / 128), 128, GSMEM_TOTAL>>>(
        KVh, KVl, Wkh, Wkl, nullptr, Kh, Kl,
        Wvh, Wvl, Vh, Vl, D_MODEL, D_MODEL, L_LAT, D_MODEL / 64);
    // [4] attention
    attn_mma<<<dim3(S_LEN / 64, NHEADS, BATCH), 128, AT_SMEM>>>(
        Qh, Ql, Kh, Kl, Vh, Vl, AOh, AOl);
    // [5] out = AO @ Wo   <-- ncu capture slot
    gemm_mma<0, 0><<<dim3(D_MODEL / 64, M_ROWS / 128), 128, GSMEM_TOTAL>>>(
        AOh, AOl, Woh, Wol, out, nullptr, nullptr,
        nullptr, nullptr, nullptr, nullptr, D_MODEL, 0, D_MODEL, 0);
}